// round 11
// baseline (speedup 1.0000x reference)
#include <cuda_runtime.h>
#include <cuda_bf16.h>
#include <math.h>

#define D     512
#define KTOP  11          // 1 + K
#define KNEI  9           // reference uses idx[1:K] = 9 neighbors
#define NCLS  100
#define RPB   256         // rows per block in fused kernel (977 blocks)
#define NMAX  250000
#define GMAX  ((NMAX + RPB - 1) / RPB)        // 977
#define NCAND (GMAX * KTOP)                   // 10747
#define MBLK  ((NCAND + 255) / 256)           // 42 merge blocks
#define NC2   (MBLK * KTOP)                   // 462

// Scratch (allocation-free rule: __device__ globals)
__device__ unsigned long long g_cand[NCAND];
__device__ unsigned long long g_cand2[NC2];

// ---- monotonic float key: bigger key == bigger value; tie -> smaller index wins ----
__device__ __forceinline__ unsigned long long make_key(float v, unsigned int idx) {
    unsigned int b = __float_as_uint(v);
    b = (b & 0x80000000u) ? ~b : (b | 0x80000000u);
    return ((unsigned long long)b << 32) | (unsigned int)(~idx);
}
__device__ __forceinline__ float key_val(unsigned long long k) {
    unsigned int o = (unsigned int)(k >> 32);
    unsigned int b = (o & 0x80000000u) ? (o ^ 0x80000000u) : ~o;
    return __uint_as_float(b);
}
__device__ __forceinline__ unsigned int key_idx(unsigned long long k) {
    return ~(unsigned int)(k & 0xFFFFFFFFu);
}

__device__ __forceinline__ unsigned long long block_max_u64(unsigned long long v,
                                                            unsigned long long* sh) {
    #pragma unroll
    for (int o = 16; o; o >>= 1) {
        unsigned long long u = __shfl_xor_sync(0xFFFFFFFFu, v, o);
        if (u > v) v = u;
    }
    int warp = threadIdx.x >> 5, lane = threadIdx.x & 31;
    if (lane == 0) sh[warp] = v;
    __syncthreads();
    if (warp == 0) {
        int nw = (blockDim.x + 31) >> 5;
        v = (lane < nw) ? sh[lane] : 0ULL;
        #pragma unroll
        for (int o = 4; o; o >>= 1) {
            unsigned long long u = __shfl_xor_sync(0xFFFFFFFFu, v, o);
            if (u > v) v = u;
        }
        if (lane == 0) sh[0] = v;
    }
    __syncthreads();
    unsigned long long r = sh[0];
    __syncthreads();
    return r;
}

// ---------- Kernel 1 (R3-exact): fused dot+sumsq streaming + per-block top-11 ----------
__global__ void score_topk_kernel(
        const float* __restrict__ coll, const float* __restrict__ emb, int n) {
    __shared__ float4 sq[D / 4];
    __shared__ unsigned long long skeys[RPB];
    __shared__ unsigned long long sh[33];

    int t = threadIdx.x;
    if (t < D / 4) sq[t] = reinterpret_cast<const float4*>(emb)[t];
    skeys[t] = 0ULL;
    __syncthreads();

    int warp = t >> 5, lane = t & 31;
    int rbeg = blockIdx.x * RPB;
    int rend = min(rbeg + RPB, n);

    for (int it = 0; it < RPB / 8; it++) {
        int local = it * 8 + warp;
        int row = rbeg + local;
        if (row >= rend) break;
        const float4* rp = reinterpret_cast<const float4*>(coll + (size_t)row * D);
        float dot = 0.f, rr = 0.f;
        #pragma unroll
        for (int j = 0; j < 4; j++) {
            float4 v = __ldcs(rp + lane + 32 * j);   // streaming: no reuse, evict-first
            float4 q = sq[lane + 32 * j];
            dot += v.x * q.x + v.y * q.y + v.z * q.z + v.w * q.w;
            rr  += v.x * v.x + v.y * v.y + v.z * v.z + v.w * v.w;
        }
        #pragma unroll
        for (int o = 16; o; o >>= 1) {
            dot += __shfl_xor_sync(0xFFFFFFFFu, dot, o);
            rr  += __shfl_xor_sync(0xFFFFFFFFu, rr, o);
        }
        if (lane == 0)
            skeys[local] = make_key(dot * rsqrtf(rr + 1e-12f), (unsigned)row);
    }
    __syncthreads();

    // block top-11 over 256 keys (1 per thread)
    for (int r = 0; r < KTOP; r++) {
        unsigned long long v = skeys[t];
        unsigned long long w = block_max_u64(v, sh);
        if (t == 0) g_cand[blockIdx.x * KTOP + r] = w;
        if (skeys[t] == w) skeys[t] = 0ULL;      // keys unique (index embedded)
        __syncthreads();
    }
}

// ---------- Kernel 2: parallel merge, 42 blocks x 256 keys -> 462 survivors ----------
__global__ void __launch_bounds__(256) merge_kernel(int ncand) {
    __shared__ unsigned long long sh[33];
    int t = threadIdx.x;
    int i = blockIdx.x * 256 + t;
    unsigned long long key = (i < ncand) ? g_cand[i] : 0ULL;

    for (int r = 0; r < KTOP; r++) {
        unsigned long long w = block_max_u64(key, sh);
        if (t == 0) g_cand2[blockIdx.x * KTOP + r] = w;
        if (key == w) key = 0ULL;                // keys unique: one owner
    }
}

// ---------- Kernel 3: final merge of 462 keys, vote, output ----------
__global__ void __launch_bounds__(256) finalize(
        const float* __restrict__ emb, const int* __restrict__ labels,
        float* __restrict__ out, int out_size) {
    __shared__ unsigned long long sh[33];
    __shared__ unsigned long long top[KTOP];
    __shared__ float sred[8];

    int t = threadIdx.x;
    unsigned long long k0 = (t < NC2) ? g_cand2[t] : 0ULL;
    unsigned long long k1 = (t + 256 < NC2) ? g_cand2[t + 256] : 0ULL;

    for (int r = 0; r < KTOP; r++) {
        unsigned long long m = k0 > k1 ? k0 : k1;
        unsigned long long w = block_max_u64(m, sh);
        if (t == 0) top[r] = w;
        if (k0 == w) k0 = 0ULL;
        if (k1 == w) k1 = 0ULL;
    }

    // ||q||^2
    float q0 = emb[t], q1 = emb[t + 256];
    float s = q0 * q0 + q1 * q1;
    #pragma unroll
    for (int o = 16; o; o >>= 1) s += __shfl_xor_sync(0xFFFFFFFFu, s, o);
    if ((t & 31) == 0) sred[t >> 5] = s;
    __syncthreads();

    if (t == 0) {
        float qq = 0.f;
        #pragma unroll
        for (int w = 0; w < 8; w++) qq += sred[w];
        float inv_q = 1.0f / sqrtf(qq + 1e-12f);

        float vals[KTOP]; int idxs[KTOP];
        #pragma unroll
        for (int i = 0; i < KTOP; i++) {
            vals[i] = key_val(top[i]) * inv_q;
            idxs[i] = (int)key_idx(top[i]);
        }
        int preds[KNEI];
        #pragma unroll
        for (int j = 0; j < KNEI; j++) preds[j] = labels[idxs[1 + j]];

        int counts[NCLS];
        #pragma unroll
        for (int c = 0; c < NCLS; c++) counts[c] = 0;
        #pragma unroll
        for (int j = 0; j < KNEI; j++) {
            int p = preds[j];
            if (p >= 0 && p < NCLS) counts[p]++;
        }
        int best = 0;
        for (int c = 1; c < NCLS; c++)
            if (counts[c] > counts[best]) best = c;   // first-occurrence argmax
        int pos = 0;
        for (int j = KNEI - 1; j >= 0; j--)
            if (preds[j] == best) pos = j;            // first match
        float conf = vals[1 + pos];

        int m = out_size < KTOP ? out_size : KTOP;
        for (int i = 0; i < m; i++) out[i] = vals[i];
        if (out_size > KTOP)     out[KTOP]     = (float)best;
        if (out_size > KTOP + 1) out[KTOP + 1] = conf;
        for (int i = KTOP + 2; i < out_size; i++) out[i] = 0.0f;
    }
}

extern "C" void kernel_launch(void* const* d_in, const int* in_sizes, int n_in,
                              void* d_out, int out_size) {
    const float* emb    = (const float*)d_in[0];
    const float* coll   = (const float*)d_in[1];
    const int*   labels = (const int*)d_in[2];   // jnp.int64 canonicalizes to int32 (no x64)
    int n = in_sizes[1] / D;   // 250000
    int grid = (n + RPB - 1) / RPB;              // 977

    score_topk_kernel<<<grid, 256>>>(coll, emb, n);
    merge_kernel<<<MBLK, 256>>>(grid * KTOP);
    finalize<<<1, 256>>>(emb, labels, (float*)d_out, out_size);
}

// round 12
// speedup vs baseline: 1.3174x; 1.3174x over previous
#include <cuda_runtime.h>
#include <cuda_bf16.h>
#include <math.h>

#define D     512
#define KTOP  11          // 1 + K
#define KNEI  9           // reference uses idx[1:K] = 9 neighbors
#define NCLS  100
#define NMAX  250000
#define SPB   1024        // scores per block in topk stage
#define GRID2 245         // ceil(250000/1024)
#define NC2   (GRID2 * KTOP)   // 2695

// Scratch (allocation-free rule: __device__ globals)
__device__ float              g_scores[NMAX];
__device__ unsigned long long g_cand[NC2];
__device__ unsigned int       g_counter;   // never reset; tested modulo GRID2

// ---- monotonic float key: bigger key == bigger value; tie -> smaller index wins ----
__device__ __forceinline__ unsigned long long make_key(float v, unsigned int idx) {
    unsigned int b = __float_as_uint(v);
    b = (b & 0x80000000u) ? ~b : (b | 0x80000000u);
    return ((unsigned long long)b << 32) | (unsigned int)(~idx);
}
__device__ __forceinline__ float key_val(unsigned long long k) {
    unsigned int o = (unsigned int)(k >> 32);
    unsigned int b = (o & 0x80000000u) ? (o ^ 0x80000000u) : ~o;
    return __uint_as_float(b);
}
__device__ __forceinline__ unsigned int key_idx(unsigned long long k) {
    return ~(unsigned int)(k & 0xFFFFFFFFu);
}

__device__ __forceinline__ unsigned long long block_max_u64(unsigned long long v,
                                                            unsigned long long* sh) {
    #pragma unroll
    for (int o = 16; o; o >>= 1) {
        unsigned long long u = __shfl_xor_sync(0xFFFFFFFFu, v, o);
        if (u > v) v = u;
    }
    int warp = threadIdx.x >> 5, lane = threadIdx.x & 31;
    if (lane == 0) sh[warp] = v;
    __syncthreads();
    if (warp == 0) {
        int nw = (blockDim.x + 31) >> 5;
        v = (lane < nw) ? sh[lane] : 0ULL;
        #pragma unroll
        for (int o = 4; o; o >>= 1) {
            unsigned long long u = __shfl_xor_sync(0xFFFFFFFFu, v, o);
            if (u > v) v = u;
        }
        if (lane == 0) sh[0] = v;
    }
    __syncthreads();
    unsigned long long r = sh[0];
    __syncthreads();
    return r;
}

// ---------- Kernel 1 (stable, measured 76us @ 85% DRAM): warp-per-row streaming ----------
__global__ void score_kernel(const float* __restrict__ coll,
                             const float* __restrict__ emb, int n) {
    __shared__ float4 sq[D / 4];
    int t = threadIdx.x;
    if (t < D / 4) sq[t] = reinterpret_cast<const float4*>(emb)[t];
    __syncthreads();

    int warp = t >> 5, lane = t & 31;
    int row = blockIdx.x * 8 + warp;
    if (row >= n) return;

    const float4* rp = reinterpret_cast<const float4*>(coll + (size_t)row * D);
    float dot = 0.f, rr = 0.f;
    #pragma unroll
    for (int j = 0; j < 4; j++) {
        float4 v = rp[lane + 32 * j];
        float4 q = sq[lane + 32 * j];
        dot += v.x * q.x + v.y * q.y + v.z * q.z + v.w * q.w;
        rr  += v.x * v.x + v.y * v.y + v.z * v.z + v.w * v.w;
    }
    #pragma unroll
    for (int o = 16; o; o >>= 1) {
        dot += __shfl_xor_sync(0xFFFFFFFFu, dot, o);
        rr  += __shfl_xor_sync(0xFFFFFFFFu, rr, o);
    }
    if (lane == 0)
        g_scores[row] = dot / sqrtf(rr + 1e-12f);   // q-norm scaling deferred (order-invariant)
}

// ---------- Kernel 2: per-block top-11 + last-block merge/vote/output (ONE kernel tail) ----------
__global__ void __launch_bounds__(256) topk_finalize(
        const float* __restrict__ emb, const int* __restrict__ labels,
        float* __restrict__ out, int out_size, int n) {
    __shared__ unsigned long long sh[33];
    __shared__ bool is_last;

    int t = threadIdx.x;
    int base = blockIdx.x * SPB;

    // per-thread 4 strided scores
    unsigned long long k[4];
    #pragma unroll
    for (int j = 0; j < 4; j++) {
        int i = base + t + j * 256;
        k[j] = (i < n) ? make_key(g_scores[i], (unsigned)i) : 0ULL;
    }
    for (int r = 0; r < KTOP; r++) {
        unsigned long long m = k[0];
        if (k[1] > m) m = k[1];
        if (k[2] > m) m = k[2];
        if (k[3] > m) m = k[3];
        unsigned long long w = block_max_u64(m, sh);
        if (t == 0) g_cand[blockIdx.x * KTOP + r] = w;
        #pragma unroll
        for (int j = 0; j < 4; j++) if (k[j] == w) k[j] = 0ULL;  // unique keys
    }

    // publish candidates, elect last block
    __threadfence();
    if (t == 0) {
        unsigned int old = atomicAdd(&g_counter, 1u);
        is_last = ((old % GRID2) == GRID2 - 1);
    }
    __syncthreads();
    if (!is_last) return;
    __threadfence();   // acquire: see all blocks' g_cand writes

    // ---- last block: merge 2695 candidates ----
    __shared__ unsigned long long scand[NC2];
    __shared__ unsigned long long top[KTOP];
    __shared__ float sred[8];

    for (int i = t; i < NC2; i += 256) scand[i] = g_cand[i];
    __syncthreads();

    for (int r = 0; r < KTOP; r++) {
        unsigned long long m = 0ULL; int am = -1;
        #pragma unroll
        for (int jj = 0; jj < (NC2 + 255) / 256; jj++) {
            int i = t + jj * 256;
            if (i < NC2) {
                unsigned long long kk = scand[i];
                if (kk > m) { m = kk; am = i; }
            }
        }
        unsigned long long w = block_max_u64(m, sh);
        if (t == 0) top[r] = w;
        if (am >= 0 && m == w) scand[am] = 0ULL;  // unique keys: one owner
        __syncthreads();
    }

    // ||q||^2
    float q0 = emb[t], q1 = emb[t + 256];
    float s = q0 * q0 + q1 * q1;
    #pragma unroll
    for (int o = 16; o; o >>= 1) s += __shfl_xor_sync(0xFFFFFFFFu, s, o);
    if ((t & 31) == 0) sred[t >> 5] = s;
    __syncthreads();

    if (t == 0) {
        float qq = 0.f;
        #pragma unroll
        for (int w = 0; w < 8; w++) qq += sred[w];
        float inv_q = 1.0f / sqrtf(qq + 1e-12f);

        float vals[KTOP]; int idxs[KTOP];
        #pragma unroll
        for (int i = 0; i < KTOP; i++) {
            vals[i] = key_val(top[i]) * inv_q;
            idxs[i] = (int)key_idx(top[i]);
        }
        int preds[KNEI];
        #pragma unroll
        for (int j = 0; j < KNEI; j++) preds[j] = labels[idxs[1 + j]];

        int counts[NCLS];
        #pragma unroll
        for (int c = 0; c < NCLS; c++) counts[c] = 0;
        #pragma unroll
        for (int j = 0; j < KNEI; j++) {
            int p = preds[j];
            if (p >= 0 && p < NCLS) counts[p]++;
        }
        int best = 0;
        for (int c = 1; c < NCLS; c++)
            if (counts[c] > counts[best]) best = c;   // first-occurrence argmax
        int pos = 0;
        for (int j = KNEI - 1; j >= 0; j--)
            if (preds[j] == best) pos = j;            // first match
        float conf = vals[1 + pos];

        int m = out_size < KTOP ? out_size : KTOP;
        for (int i = 0; i < m; i++) out[i] = vals[i];
        if (out_size > KTOP)     out[KTOP]     = (float)best;
        if (out_size > KTOP + 1) out[KTOP + 1] = conf;
        for (int i = KTOP + 2; i < out_size; i++) out[i] = 0.0f;
    }
}

extern "C" void kernel_launch(void* const* d_in, const int* in_sizes, int n_in,
                              void* d_out, int out_size) {
    const float* emb    = (const float*)d_in[0];
    const float* coll   = (const float*)d_in[1];
    const int*   labels = (const int*)d_in[2];   // jnp.int64 canonicalizes to int32 (no x64)
    int n = in_sizes[1] / D;   // 250000

    score_kernel<<<(n + 7) / 8, 256>>>(coll, emb, n);
    topk_finalize<<<GRID2, 256>>>(emb, labels, (float*)d_out, out_size, n);
}

// round 13
// speedup vs baseline: 1.3268x; 1.0071x over previous
#include <cuda_runtime.h>
#include <cuda_bf16.h>
#include <math.h>

#define D     512
#define KTOP  11          // 1 + K
#define KNEI  9           // reference uses idx[1:K] = 9 neighbors
#define NCLS  100
#define NMAX  250000
#define GRID2 128         // tail blocks (one wave)
#define TPB2  1024
#define SPB2  2048        // scores per tail block (128*2048 = 262144 >= N)
#define NC2   (GRID2 * KTOP)   // 1408

// Scratch (allocation-free rule: __device__ globals)
__device__ float              g_scores[NMAX];
__device__ unsigned long long g_cand[NC2];
__device__ unsigned int       g_counter;   // never reset; tested modulo GRID2

// ---- monotonic float key: bigger key == bigger value; tie -> smaller index wins ----
__device__ __forceinline__ unsigned long long make_key(float v, unsigned int idx) {
    unsigned int b = __float_as_uint(v);
    b = (b & 0x80000000u) ? ~b : (b | 0x80000000u);
    return ((unsigned long long)b << 32) | (unsigned int)(~idx);
}
__device__ __forceinline__ float key_val(unsigned long long k) {
    unsigned int o = (unsigned int)(k >> 32);
    unsigned int b = (o & 0x80000000u) ? (o ^ 0x80000000u) : ~o;
    return __uint_as_float(b);
}
__device__ __forceinline__ unsigned int key_idx(unsigned long long k) {
    return ~(unsigned int)(k & 0xFFFFFFFFu);
}

__device__ __forceinline__ unsigned long long warp_max_u64(unsigned long long v) {
    #pragma unroll
    for (int o = 16; o; o >>= 1) {
        unsigned long long u = __shfl_xor_sync(0xFFFFFFFFu, v, o);
        if (u > v) v = u;
    }
    return v;
}

// ---------- Kernel 1 (stable, measured 76us @ 85% DRAM): warp-per-row streaming ----------
__global__ void score_kernel(const float* __restrict__ coll,
                             const float* __restrict__ emb, int n) {
    __shared__ float4 sq[D / 4];
    int t = threadIdx.x;
    if (t < D / 4) sq[t] = reinterpret_cast<const float4*>(emb)[t];
    __syncthreads();

    int warp = t >> 5, lane = t & 31;
    int row = blockIdx.x * 8 + warp;
    if (row >= n) return;

    const float4* rp = reinterpret_cast<const float4*>(coll + (size_t)row * D);
    float dot = 0.f, rr = 0.f;
    #pragma unroll
    for (int j = 0; j < 4; j++) {
        float4 v = rp[lane + 32 * j];
        float4 q = sq[lane + 32 * j];
        dot += v.x * q.x + v.y * q.y + v.z * q.z + v.w * q.w;
        rr  += v.x * v.x + v.y * v.y + v.z * v.z + v.w * v.w;
    }
    #pragma unroll
    for (int o = 16; o; o >>= 1) {
        dot += __shfl_xor_sync(0xFFFFFFFFu, dot, o);
        rr  += __shfl_xor_sync(0xFFFFFFFFu, rr, o);
    }
    if (lane == 0)
        g_scores[row] = dot / sqrtf(rr + 1e-12f);   // q-norm scaling deferred (order-invariant)
}

// ---------- Kernel 2: barrier-free warp-local top-k + last-block vote (ONE kernel tail) ----------
__global__ void __launch_bounds__(TPB2) topk_finalize(
        const float* __restrict__ emb, const int* __restrict__ labels,
        float* __restrict__ out, int out_size, int n) {
    __shared__ unsigned long long swin[32 * KTOP];   // stage-1 winners per warp
    __shared__ unsigned long long top[KTOP];
    __shared__ float sred[32];
    __shared__ bool is_last;

    int t = threadIdx.x;
    int warp = t >> 5, lane = t & 31;

    // ---- Phase A: warp-local top-11 over 64 scores (2 keys/lane), shfl-only ----
    {
        int base = blockIdx.x * SPB2 + warp * 64;
        int i0 = base + lane, i1 = base + 32 + lane;
        unsigned long long k0 = (i0 < n) ? make_key(g_scores[i0], (unsigned)i0) : 0ULL;
        unsigned long long k1 = (i1 < n) ? make_key(g_scores[i1], (unsigned)i1) : 0ULL;
        #pragma unroll
        for (int r = 0; r < KTOP; r++) {
            unsigned long long m = k0 > k1 ? k0 : k1;
            unsigned long long w = warp_max_u64(m);
            if (lane == 0) swin[warp * KTOP + r] = w;
            if (k0 == w) k0 = 0ULL;
            if (k1 == w) k1 = 0ULL;
        }
    }
    __syncthreads();

    // ---- Phase B: warp 0 merges 352 winners (11 keys/lane), shfl-only ----
    if (warp == 0) {
        unsigned long long k[KTOP];
        #pragma unroll
        for (int j = 0; j < KTOP; j++) k[j] = swin[lane * KTOP + j];
        #pragma unroll
        for (int r = 0; r < KTOP; r++) {
            unsigned long long m = k[0];
            #pragma unroll
            for (int j = 1; j < KTOP; j++) if (k[j] > m) m = k[j];
            unsigned long long w = warp_max_u64(m);
            if (lane == 0) g_cand[blockIdx.x * KTOP + r] = w;
            #pragma unroll
            for (int j = 0; j < KTOP; j++) if (k[j] == w) k[j] = 0ULL;
        }
    }

    // ---- publish + elect last block ----
    __threadfence();
    if (t == 0) {
        unsigned int old = atomicAdd(&g_counter, 1u);
        is_last = ((old % GRID2) == GRID2 - 1);
    }
    __syncthreads();
    if (!is_last) return;
    __threadfence();   // acquire: see all blocks' g_cand writes

    // ---- last block: two-stage warp-local merge of 1408 keys ----
    {
        // stage 1: each warp takes 44 keys (2/lane, second partially valid)
        int base = warp * 44;
        int i0 = base + lane, i1 = base + 32 + lane;
        unsigned long long k0 = (i0 < (warp + 1) * 44 && i0 < NC2) ? g_cand[i0] : 0ULL;
        unsigned long long k1 = (i1 < (warp + 1) * 44 && i1 < NC2) ? g_cand[i1] : 0ULL;
        #pragma unroll
        for (int r = 0; r < KTOP; r++) {
            unsigned long long m = k0 > k1 ? k0 : k1;
            unsigned long long w = warp_max_u64(m);
            if (lane == 0) swin[warp * KTOP + r] = w;
            if (k0 == w) k0 = 0ULL;
            if (k1 == w) k1 = 0ULL;
        }
    }

    // ||q||^2 (overlap: all warps)
    {
        float q = (t < D) ? emb[t] : 0.f;
        float s = q * q;
        #pragma unroll
        for (int o = 16; o; o >>= 1) s += __shfl_xor_sync(0xFFFFFFFFu, s, o);
        if (lane == 0) sred[warp] = s;
    }
    __syncthreads();

    if (warp == 0) {
        unsigned long long k[KTOP];
        #pragma unroll
        for (int j = 0; j < KTOP; j++) k[j] = swin[lane * KTOP + j];
        #pragma unroll
        for (int r = 0; r < KTOP; r++) {
            unsigned long long m = k[0];
            #pragma unroll
            for (int j = 1; j < KTOP; j++) if (k[j] > m) m = k[j];
            unsigned long long w = warp_max_u64(m);
            if (lane == 0) top[r] = w;
            #pragma unroll
            for (int j = 0; j < KTOP; j++) if (k[j] == w) k[j] = 0ULL;
        }

        if (lane == 0) {
            float qq = 0.f;
            #pragma unroll
            for (int w = 0; w < 32; w++) qq += sred[w];
            float inv_q = 1.0f / sqrtf(qq + 1e-12f);

            float vals[KTOP]; int idxs[KTOP];
            #pragma unroll
            for (int i = 0; i < KTOP; i++) {
                vals[i] = key_val(top[i]) * inv_q;
                idxs[i] = (int)key_idx(top[i]);
            }
            int preds[KNEI];
            #pragma unroll
            for (int j = 0; j < KNEI; j++) preds[j] = labels[idxs[1 + j]];

            int counts[NCLS];
            #pragma unroll
            for (int c = 0; c < NCLS; c++) counts[c] = 0;
            #pragma unroll
            for (int j = 0; j < KNEI; j++) {
                int p = preds[j];
                if (p >= 0 && p < NCLS) counts[p]++;
            }
            int best = 0;
            for (int c = 1; c < NCLS; c++)
                if (counts[c] > counts[best]) best = c;   // first-occurrence argmax
            int pos = 0;
            for (int j = KNEI - 1; j >= 0; j--)
                if (preds[j] == best) pos = j;            // first match
            float conf = vals[1 + pos];

            int m = out_size < KTOP ? out_size : KTOP;
            for (int i = 0; i < m; i++) out[i] = vals[i];
            if (out_size > KTOP)     out[KTOP]     = (float)best;
            if (out_size > KTOP + 1) out[KTOP + 1] = conf;
            for (int i = KTOP + 2; i < out_size; i++) out[i] = 0.0f;
        }
    }
}

extern "C" void kernel_launch(void* const* d_in, const int* in_sizes, int n_in,
                              void* d_out, int out_size) {
    const float* emb    = (const float*)d_in[0];
    const float* coll   = (const float*)d_in[1];
    const int*   labels = (const int*)d_in[2];   // jnp.int64 canonicalizes to int32 (no x64)
    int n = in_sizes[1] / D;   // 250000

    score_kernel<<<(n + 7) / 8, 256>>>(coll, emb, n);
    topk_finalize<<<GRID2, TPB2>>>(emb, labels, (float*)d_out, out_size, n);
}